// round 16
// baseline (speedup 1.0000x reference)
#include <cuda_runtime.h>
#include <cuda_fp16.h>
#include <cstdint>

#define HH      768
#define WW      768
#define BN_EPS  1e-3f

// ---------------- device scratch (no allocations allowed) -------------------
__device__ __half g_patch[256ULL * 50 * 50 * 64];  // [blk][r][c][ci]: 2500 rows x 128B per block
__device__ __half g_wh[9 * 64 * 64];               // [j][co][ci], XOR-swizzled rows
__device__ float  g_scale[64];
__device__ float  g_bias[64];
__device__ int    g_mask[512];
__device__ int    g_inact[512];
__device__ int    g_ninact;

__device__ __forceinline__ uint32_t s2u(const void* p) {
    uint32_t a;
    asm("{ .reg .u64 t; cvta.to.shared.u64 t, %1; cvt.u32.u64 %0, t; }"
        : "=r"(a) : "l"(p));
    return a;
}

// smem map (bytes, dynamic)
#define OFF_SCALE  0
#define OFF_BIAS   256
#define OFF_B      1024            // 9 * 8192 = 73728
#define OFF_A0     74752           // 2 stages x 47616 (372 rows x 128B)
#define ASTAGE     47616
#define SMEM_TOTAL 169984

// ---------------------------------------------------------------------------
// prep: swizzled fp16 weights [j][co][ci], BN folded scale/bias
// ---------------------------------------------------------------------------
__global__ void prep_kernel(const float* __restrict__ w,
                            const float* __restrict__ conv_b,
                            const float* __restrict__ gamma,
                            const float* __restrict__ beta,
                            const float* __restrict__ mean,
                            const float* __restrict__ var) {
    int tid = blockIdx.x * blockDim.x + threadIdx.x;
    for (int i = tid; i < 9 * 64 * 64; i += gridDim.x * blockDim.x) {
        int ci = i & 63, co = (i >> 6) & 63, j = i >> 12;
        int kh = j / 3, kw = j % 3;
        float v = w[((co * 64 + ci) * 3 + kh) * 3 + kw];
        int u  = ci >> 3;
        int su = u ^ (co & 7);               // XOR swizzle within 128B row
        g_wh[j * 4096 + co * 64 + su * 8 + (ci & 7)] = __float2half_rn(v);
    }
    if (tid < 64) {
        float inv = gamma[tid] * rsqrtf(var[tid] + BN_EPS);
        g_scale[tid] = inv;
        g_bias[tid]  = beta[tid] + (conv_b[tid] - mean[tid]) * inv;
    }
}

// ---------------------------------------------------------------------------
// mask: mark active blocks, then build the inactive-block list
// ---------------------------------------------------------------------------
__global__ void mask_kernel(const int* __restrict__ abi, int nblk) {
    int t = threadIdx.x;
    if (t == 0) g_ninact = 0;
    if (t < 512) g_mask[t] = 0;
    __syncthreads();
    if (t < nblk) {
        int n = abi[3 * t], bh = abi[3 * t + 1], bw = abi[3 * t + 2];
        g_mask[(n << 8) + (bh << 4) + bw] = 1;
    }
    __syncthreads();
    if (t < 512 && !g_mask[t]) {
        int pos = atomicAdd(&g_ninact, 1);
        g_inact[pos] = t;
    }
}

// ---------------------------------------------------------------------------
// conv: FUSED patch-gather + implicit GEMM (mma.sync m16n8k16 fp16) + zeroing.
// CTAs [0, nblk): prologue gathers this block's 50x50x64 input patch
// (fp32 -> fp16 NHWC, pad-halo) into g_patch[b], then runs the R12 GEMM:
// 9 M-tiles of 256 pos x 64 cout, 512 threads = 16 warps (8m x 2n),
// warp tile 32x32, double-buffered contiguous-A staging.
// Patch DRAM traffic now overlaps conv compute across staggered waves.
// CTAs [nblk, ...): zero one inactive 48x48x64 output region each.
// ---------------------------------------------------------------------------
__global__ void __launch_bounds__(512, 1)
conv_kernel(const float* __restrict__ x, const int* __restrict__ abi,
            float* __restrict__ out, int nblk) {
    const int tid = threadIdx.x;
    const int b = blockIdx.x;

    // ---- zero branch: inactive blocks ----
    if (b >= nblk) {
        int k = b - nblk;
        if (k < g_ninact) {
            int blk = g_inact[k];
            int zn = blk >> 8, zbh = (blk >> 4) & 15, zbw = blk & 15;
            const float4 z = make_float4(0.f, 0.f, 0.f, 0.f);
            for (int i = tid; i < 36864; i += 512) {
                int q = i % 12, row = (i / 12) % 48, c = i / (12 * 48);
                float4* p = reinterpret_cast<float4*>(
                    out + (((size_t)(zn * 64 + c) * HH + zbh * 48 + row) * WW
                           + zbw * 48)) + q;
                *p = z;
            }
        }
        return;
    }

    extern __shared__ __align__(1024) char smem[];
    const uint32_t sb = s2u(smem);
    const int n = abi[3 * b], bh = abi[3 * b + 1], bw = abi[3 * b + 2];

    // stage all 9 weight chunks (73728 B = 4608 uint4)
    {
        const uint4* src = reinterpret_cast<const uint4*>(g_wh);
        uint4* dst = reinterpret_cast<uint4*>(smem + OFF_B);
        #pragma unroll
        for (int i = 0; i < 9; i++) dst[tid + 512 * i] = src[tid + 512 * i];
    }
    if (tid < 64) {
        reinterpret_cast<float*>(smem + OFF_SCALE)[tid] = g_scale[tid];
        reinterpret_cast<float*>(smem + OFF_BIAS)[tid]  = g_bias[tid];
    }

    // ---- fused patch gather: 2 rows per iteration through smem staging ----
    {
        __half* srows = reinterpret_cast<__half*>(smem + OFF_A0);  // [2][64][51]
        const int half_id = tid >> 8;        // 0 or 1: which of the 2 rows
        const int t  = tid & 255;
        const int c  = t & 63;               // patch column
        const int cg = t >> 6;               // ci group (16 ch each)
        const int gc = bw * 48 - 1 + c;
        const size_t stride = (size_t)HH * WW;

        for (int it = 0; it < 25; it++) {
            const int r  = it * 2 + half_id;
            const int gr = bh * 48 - 1 + r;
            const bool rok = (unsigned)gr < (unsigned)HH;
            const bool ok  = rok && (c < 50) && ((unsigned)gc < (unsigned)WW);
            const float* src = x + ((size_t)(n * 64 + cg * 16) * HH
                                    + (rok ? gr : 0)) * WW + (ok ? gc : 0);
            if (c < 50) {
                #pragma unroll
                for (int k = 0; k < 16; k++) {
                    float v = ok ? __ldg(src) : 0.f;
                    srows[(half_id * 64 + cg * 16 + k) * 51 + c] = __float2half_rn(v);
                    src += stride;
                }
            }
            __syncthreads();
            __half2* dst = reinterpret_cast<__half2*>(
                g_patch + ((size_t)(b * 50 + r) * 50) * 64);
            const int ci2 = t & 31;
            const int c0q = t >> 5;
            #pragma unroll 2
            for (int cc = c0q; cc < 50; cc += 8)
                dst[cc * 32 + ci2] = __halves2half2(
                    srows[(half_id * 64 + 2 * ci2) * 51 + cc],
                    srows[(half_id * 64 + 2 * ci2 + 1) * 51 + cc]);
            __syncthreads();
        }
    }
    // __syncthreads above makes this CTA's g_patch writes visible to its own
    // cp.async reads below (L2-coherent path).

    const int lane = tid & 31;
    const int w    = tid >> 5;
    const int m_warp = w & 7;            // 8 m-warps of 32 rows
    const int n_warp = w >> 3;           // 2 n-warps of 32 cols

    const int a_r  = lane & 15;
    const int a_uh = lane >> 4;
    const int b_n  = (lane & 7) + ((lane >> 4) << 3);
    const int b_uh = (lane >> 3) & 1;

    uint64_t pbase;
    {
        const __half* pb = g_patch + (size_t)b * 2500 * 64;
        asm("cvta.to.global.u64 %0, %1;" : "=l"(pbase) : "l"(pb));
    }

    // issue cp.async for one tile's A region (372 rows) into stage (tl&1)
    auto issue_tile = [&](int tl) {
        const int p0 = tl * 256;
        const int lb = p0 + 2 * (p0 / 48);          // patch-linear base row
        const uint32_t abase = sb + OFF_A0 + (tl & 1) * ASTAGE;
        #pragma unroll
        for (int it = 0; it < 6; it++) {
            int i = tid + it * 512;                  // 372*8 = 2976 units
            if (i < 2976) {
                int lam = i >> 3, u = i & 7;
                int lsrc = lb + lam;
                if (lsrc > 2499) lsrc = 2499;        // clamp (rows unused by gemm)
                uint32_t dst = abase + (uint32_t)(lam * 128 + ((u ^ (lam & 7)) * 16));
                uint64_t src = pbase + (uint64_t)lsrc * 128 + (uint64_t)u * 16;
                asm volatile("cp.async.cg.shared.global [%0], [%1], 16;"
                             :: "r"(dst), "l"(src) : "memory");
            }
        }
        asm volatile("cp.async.commit_group;" ::: "memory");
    };

    issue_tile(0);   // prologue

    const float* ssc = reinterpret_cast<const float*>(smem + OFF_SCALE);
    const float* sbi = reinterpret_cast<const float*>(smem + OFF_BIAS);

    for (int tl = 0; tl < 9; tl++) {
        asm volatile("cp.async.wait_group 0;" ::: "memory");
        __syncthreads();
        if (tl < 8) issue_tile(tl + 1);   // overlaps with this tile's gemm

        const int p0 = tl * 256;
        const int l0 = p0 + 2 * (p0 / 48);
        const int pf0 = p0 + m_warp * 32 + a_r;
        const int lb0 = pf0 + 2 * (pf0 / 48) - l0;   // lane's linear row, m16 tile 0
        const int pf1 = pf0 + 16;
        const int lb1 = pf1 + 2 * (pf1 / 48) - l0;   // m16 tile 1
        const uint32_t abase = sb + OFF_A0 + (tl & 1) * ASTAGE;

        float d[2][4][4];
        #pragma unroll
        for (int a = 0; a < 2; a++)
            #pragma unroll
            for (int cq = 0; cq < 4; cq++)
                #pragma unroll
                for (int e = 0; e < 4; e++) d[a][cq][e] = 0.f;

        #pragma unroll
        for (int j = 0; j < 9; j++) {
            const int joff = (j / 3) * 50 + (j % 3);
            const int la0 = lb0 + joff;
            const int la1 = lb1 + joff;
            const uint32_t r0base = abase + (uint32_t)(la0 * 128);
            const uint32_t r1base = abase + (uint32_t)(la1 * 128);
            const uint32_t sw0 = (uint32_t)((la0 & 7) * 16);
            const uint32_t sw1 = (uint32_t)((la1 & 7) * 16);
            const uint32_t bbase = sb + OFF_B + j * 8192;

            #pragma unroll
            for (int ks = 0; ks < 4; ks++) {
                uint32_t a0[4], a1[4];
                {
                    uint32_t addr = r0base + ((uint32_t)((ks * 2 + a_uh) * 16) ^ sw0);
                    asm volatile("ldmatrix.sync.aligned.m8n8.x4.shared.b16 "
                                 "{%0,%1,%2,%3}, [%4];"
                                 : "=r"(a0[0]), "=r"(a0[1]), "=r"(a0[2]), "=r"(a0[3])
                                 : "r"(addr));
                    addr = r1base + ((uint32_t)((ks * 2 + a_uh) * 16) ^ sw1);
                    asm volatile("ldmatrix.sync.aligned.m8n8.x4.shared.b16 "
                                 "{%0,%1,%2,%3}, [%4];"
                                 : "=r"(a1[0]), "=r"(a1[1]), "=r"(a1[2]), "=r"(a1[3])
                                 : "r"(addr));
                }
                uint32_t bf[4][2];
                {
                    int nn = n_warp * 32 + b_n;
                    uint32_t addr = bbase + (uint32_t)(nn * 128 +
                                    (((ks * 2 + b_uh) ^ (nn & 7)) * 16));
                    asm volatile("ldmatrix.sync.aligned.m8n8.x4.shared.b16 "
                                 "{%0,%1,%2,%3}, [%4];"
                                 : "=r"(bf[0][0]), "=r"(bf[0][1]),
                                   "=r"(bf[1][0]), "=r"(bf[1][1])
                                 : "r"(addr));
                    nn += 16;
                    addr = bbase + (uint32_t)(nn * 128 +
                           (((ks * 2 + b_uh) ^ (nn & 7)) * 16));
                    asm volatile("ldmatrix.sync.aligned.m8n8.x4.shared.b16 "
                                 "{%0,%1,%2,%3}, [%4];"
                                 : "=r"(bf[2][0]), "=r"(bf[2][1]),
                                   "=r"(bf[3][0]), "=r"(bf[3][1])
                                 : "r"(addr));
                }
                #pragma unroll
                for (int nt = 0; nt < 4; nt++) {
                    asm volatile("mma.sync.aligned.m16n8k16.row.col.f32.f16.f16.f32 "
                                 "{%0,%1,%2,%3}, {%4,%5,%6,%7}, {%8,%9}, {%0,%1,%2,%3};"
                                 : "+f"(d[0][nt][0]), "+f"(d[0][nt][1]),
                                   "+f"(d[0][nt][2]), "+f"(d[0][nt][3])
                                 : "r"(a0[0]), "r"(a0[1]), "r"(a0[2]), "r"(a0[3]),
                                   "r"(bf[nt][0]), "r"(bf[nt][1]));
                    asm volatile("mma.sync.aligned.m16n8k16.row.col.f32.f16.f16.f32 "
                                 "{%0,%1,%2,%3}, {%4,%5,%6,%7}, {%8,%9}, {%0,%1,%2,%3};"
                                 : "+f"(d[1][nt][0]), "+f"(d[1][nt][1]),
                                   "+f"(d[1][nt][2]), "+f"(d[1][nt][3])
                                 : "r"(a1[0]), "r"(a1[1]), "r"(a1[2]), "r"(a1[3]),
                                   "r"(bf[nt][0]), "r"(bf[nt][1]));
                }
            }
        }

        // ---- epilogue: BN + ReLU + store (R12 form; overlaps next staging) ----
        #pragma unroll
        for (int m16 = 0; m16 < 2; m16++) {
            #pragma unroll
            for (int nt = 0; nt < 4; nt++) {
                #pragma unroll
                for (int e = 0; e < 4; e++) {
                    int rloc = m_warp * 32 + m16 * 16 + (lane >> 2) + ((e >> 1) << 3);
                    int c    = n_warp * 32 + nt * 8 + (lane & 3) * 2 + (e & 1);
                    int pp   = p0 + rloc;
                    int r0   = pp / 48;
                    int er   = bh * 48 + r0;
                    int ec   = bw * 48 + (pp - r0 * 48);
                    float v  = fmaxf(fmaf(d[m16][nt][e], ssc[c], sbi[c]), 0.f);
                    out[((size_t)(n * 64 + c) * HH + er) * WW + ec] = v;
                }
            }
        }
    }
}

// ---------------------------------------------------------------------------
extern "C" void kernel_launch(void* const* d_in, const int* in_sizes, int n_in,
                              void* d_out, int out_size) {
    const float* x      = (const float*)d_in[0];
    const float* conv_w = (const float*)d_in[1];
    const float* conv_b = (const float*)d_in[2];
    const float* gamma  = (const float*)d_in[3];
    const float* beta   = (const float*)d_in[4];
    const float* rmean  = (const float*)d_in[5];
    const float* rvar   = (const float*)d_in[6];
    const int*   abi    = (const int*)d_in[7];
    float* out = (float*)d_out;

    int nblk = in_sizes[7] / 3;   // 256

    cudaFuncSetAttribute(conv_kernel,
                         cudaFuncAttributeMaxDynamicSharedMemorySize, SMEM_TOTAL);

    prep_kernel<<<36, 1024>>>(conv_w, conv_b, gamma, beta, rmean, rvar);
    mask_kernel<<<1, 512>>>(abi, nblk);
    conv_kernel<<<512, 512, SMEM_TOTAL>>>(x, abi, out, nblk);
}

// round 17
// speedup vs baseline: 1.2781x; 1.2781x over previous
#include <cuda_runtime.h>
#include <cuda_fp16.h>
#include <cstdint>

#define HH      768
#define WW      768
#define BN_EPS  1e-3f

// ---------------- device scratch (no allocations allowed) -------------------
__device__ __half g_patch[256ULL * 50 * 50 * 64];  // [blk][r][c][ci]: 2500 rows x 128B per block
__device__ __half g_wh[9 * 64 * 64];               // [j][co][ci], XOR-swizzled rows
__device__ float  g_scale[64];
__device__ float  g_bias[64];
__device__ int    g_mask[512];
__device__ int    g_inact[512];
__device__ int    g_ninact;

__device__ __forceinline__ uint32_t s2u(const void* p) {
    uint32_t a;
    asm("{ .reg .u64 t; cvta.to.shared.u64 t, %1; cvt.u32.u64 %0, t; }"
        : "=r"(a) : "l"(p));
    return a;
}

// smem map (bytes, dynamic)
#define OFF_SCALE  0
#define OFF_BIAS   256
#define OFF_B      1024            // 9 * 8192 = 73728
#define OFF_A0     74752           // 2 stages x 47616 (372 rows x 128B)
#define ASTAGE     47616
#define SMEM_TOTAL 169984

// ---------------------------------------------------------------------------
// prep: swizzled fp16 weights [j][co][ci], BN folded scale/bias
// ---------------------------------------------------------------------------
__global__ void prep_kernel(const float* __restrict__ w,
                            const float* __restrict__ conv_b,
                            const float* __restrict__ gamma,
                            const float* __restrict__ beta,
                            const float* __restrict__ mean,
                            const float* __restrict__ var) {
    int tid = blockIdx.x * blockDim.x + threadIdx.x;
    for (int i = tid; i < 9 * 64 * 64; i += gridDim.x * blockDim.x) {
        int ci = i & 63, co = (i >> 6) & 63, j = i >> 12;
        int kh = j / 3, kw = j % 3;
        float v = w[((co * 64 + ci) * 3 + kh) * 3 + kw];
        int u  = ci >> 3;
        int su = u ^ (co & 7);               // XOR swizzle within 128B row
        g_wh[j * 4096 + co * 64 + su * 8 + (ci & 7)] = __float2half_rn(v);
    }
    if (tid < 64) {
        float inv = gamma[tid] * rsqrtf(var[tid] + BN_EPS);
        g_scale[tid] = inv;
        g_bias[tid]  = beta[tid] + (conv_b[tid] - mean[tid]) * inv;
    }
}

// ---------------------------------------------------------------------------
// mask: mark active blocks, then build the inactive-block list
// ---------------------------------------------------------------------------
__global__ void mask_kernel(const int* __restrict__ abi, int nblk) {
    int t = threadIdx.x;
    if (t == 0) g_ninact = 0;
    if (t < 512) g_mask[t] = 0;
    __syncthreads();
    if (t < nblk) {
        int n = abi[3 * t], bh = abi[3 * t + 1], bw = abi[3 * t + 2];
        g_mask[(n << 8) + (bh << 4) + bw] = 1;
    }
    __syncthreads();
    if (t < 512 && !g_mask[t]) {
        int pos = atomicAdd(&g_ninact, 1);
        g_inact[pos] = t;
    }
}

// ---------------------------------------------------------------------------
// patch: gather active-block input (with pad-halo) into NHWC fp16 patches.
// 512 threads, TWO rows per CTA (independent halves, one shared barrier):
// halves launch/drain overhead of the 12800-CTA version, doubles in-flight
// LDGs per SM. Inner maps identical to the proven R12 kernel.
// ---------------------------------------------------------------------------
__global__ __launch_bounds__(512)
void patch_kernel(const float* __restrict__ x, const int* __restrict__ abi) {
    __shared__ __half s[2][64][51];
    const int b = blockIdx.y;
    const int n = abi[3 * b], bh = abi[3 * b + 1], bw = abi[3 * b + 2];

    const int half_id = threadIdx.x >> 8;      // 0/1: which row
    const int t   = threadIdx.x & 255;
    const int r   = blockIdx.x * 2 + half_id;
    const int gr  = bh * 48 - 1 + r;
    const int gc0 = bw * 48 - 1;
    const bool rok = (unsigned)gr < (unsigned)HH;

    const int c   = t & 63;
    const int cg  = t >> 6;
    const int gc  = gc0 + c;
    const bool ok = rok && (c < 50) && ((unsigned)gc < (unsigned)WW);

    const float* src = x + ((size_t)(n * 64 + cg * 16) * HH + (rok ? gr : 0)) * WW
                         + (ok ? gc : 0);
    const size_t stride = (size_t)HH * WW;

    if (c < 50) {
        #pragma unroll
        for (int it = 0; it < 16; it++) {
            float v = ok ? __ldg(src) : 0.f;
            s[half_id][cg * 16 + it][c] = __float2half_rn(v);
            src += stride;
        }
    }
    __syncthreads();

    __half2* dst = reinterpret_cast<__half2*>(g_patch + ((size_t)(b * 50 + r) * 50) * 64);
    const int ci2 = t & 31;
    const int c0  = t >> 5;
    #pragma unroll 2
    for (int cc = c0; cc < 50; cc += 8)
        dst[cc * 32 + ci2] = __halves2half2(s[half_id][2 * ci2][cc],
                                            s[half_id][2 * ci2 + 1][cc]);
}

// ---------------------------------------------------------------------------
// conv: implicit GEMM via mma.sync m16n8k16 fp16, fused zeroing (R12 exact).
// CTA = ONE block: 9 M-tiles of 256 pos x 64 cout, 512 threads,
// 16 warps (8m x 2n), warp tile 32x32, double-buffered contiguous-A staging.
// CTAs [nblk, ...): zero one inactive 48x48x64 output region each.
// ---------------------------------------------------------------------------
__global__ void __launch_bounds__(512, 1)
conv_kernel(const int* __restrict__ abi, float* __restrict__ out, int nblk) {
    const int tid = threadIdx.x;
    const int b = blockIdx.x;

    // ---- zero branch: inactive blocks ----
    if (b >= nblk) {
        int k = b - nblk;
        if (k < g_ninact) {
            int blk = g_inact[k];
            int zn = blk >> 8, zbh = (blk >> 4) & 15, zbw = blk & 15;
            const float4 z = make_float4(0.f, 0.f, 0.f, 0.f);
            for (int i = tid; i < 36864; i += 512) {
                int q = i % 12, row = (i / 12) % 48, c = i / (12 * 48);
                float4* p = reinterpret_cast<float4*>(
                    out + (((size_t)(zn * 64 + c) * HH + zbh * 48 + row) * WW
                           + zbw * 48)) + q;
                *p = z;
            }
        }
        return;
    }

    extern __shared__ __align__(1024) char smem[];
    const uint32_t sb = s2u(smem);
    const int n = abi[3 * b], bh = abi[3 * b + 1], bw = abi[3 * b + 2];

    // stage all 9 weight chunks (73728 B = 4608 uint4)
    {
        const uint4* src = reinterpret_cast<const uint4*>(g_wh);
        uint4* dst = reinterpret_cast<uint4*>(smem + OFF_B);
        #pragma unroll
        for (int i = 0; i < 9; i++) dst[tid + 512 * i] = src[tid + 512 * i];
    }
    if (tid < 64) {
        reinterpret_cast<float*>(smem + OFF_SCALE)[tid] = g_scale[tid];
        reinterpret_cast<float*>(smem + OFF_BIAS)[tid]  = g_bias[tid];
    }

    const int lane = tid & 31;
    const int w    = tid >> 5;
    const int m_warp = w & 7;            // 8 m-warps of 32 rows
    const int n_warp = w >> 3;           // 2 n-warps of 32 cols

    const int a_r  = lane & 15;
    const int a_uh = lane >> 4;
    const int b_n  = (lane & 7) + ((lane >> 4) << 3);
    const int b_uh = (lane >> 3) & 1;

    uint64_t pbase;
    {
        const __half* pb = g_patch + (size_t)b * 2500 * 64;
        asm("cvta.to.global.u64 %0, %1;" : "=l"(pbase) : "l"(pb));
    }

    // issue cp.async for one tile's A region (372 rows) into stage (tl&1)
    auto issue_tile = [&](int tl) {
        const int p0 = tl * 256;
        const int lb = p0 + 2 * (p0 / 48);          // patch-linear base row
        const uint32_t abase = sb + OFF_A0 + (tl & 1) * ASTAGE;
        #pragma unroll
        for (int it = 0; it < 6; it++) {
            int i = tid + it * 512;                  // 372*8 = 2976 units
            if (i < 2976) {
                int lam = i >> 3, u = i & 7;
                int lsrc = lb + lam;
                if (lsrc > 2499) lsrc = 2499;        // clamp (rows unused by gemm)
                uint32_t dst = abase + (uint32_t)(lam * 128 + ((u ^ (lam & 7)) * 16));
                uint64_t src = pbase + (uint64_t)lsrc * 128 + (uint64_t)u * 16;
                asm volatile("cp.async.cg.shared.global [%0], [%1], 16;"
                             :: "r"(dst), "l"(src) : "memory");
            }
        }
        asm volatile("cp.async.commit_group;" ::: "memory");
    };

    issue_tile(0);   // prologue

    const float* ssc = reinterpret_cast<const float*>(smem + OFF_SCALE);
    const float* sbi = reinterpret_cast<const float*>(smem + OFF_BIAS);

    for (int tl = 0; tl < 9; tl++) {
        asm volatile("cp.async.wait_group 0;" ::: "memory");
        __syncthreads();
        if (tl < 8) issue_tile(tl + 1);   // overlaps with this tile's gemm

        const int p0 = tl * 256;
        const int l0 = p0 + 2 * (p0 / 48);
        const int pf0 = p0 + m_warp * 32 + a_r;
        const int lb0 = pf0 + 2 * (pf0 / 48) - l0;   // lane's linear row, m16 tile 0
        const int pf1 = pf0 + 16;
        const int lb1 = pf1 + 2 * (pf1 / 48) - l0;   // m16 tile 1
        const uint32_t abase = sb + OFF_A0 + (tl & 1) * ASTAGE;

        float d[2][4][4];
        #pragma unroll
        for (int a = 0; a < 2; a++)
            #pragma unroll
            for (int cq = 0; cq < 4; cq++)
                #pragma unroll
                for (int e = 0; e < 4; e++) d[a][cq][e] = 0.f;

        #pragma unroll
        for (int j = 0; j < 9; j++) {
            const int joff = (j / 3) * 50 + (j % 3);
            const int la0 = lb0 + joff;
            const int la1 = lb1 + joff;
            const uint32_t r0base = abase + (uint32_t)(la0 * 128);
            const uint32_t r1base = abase + (uint32_t)(la1 * 128);
            const uint32_t sw0 = (uint32_t)((la0 & 7) * 16);
            const uint32_t sw1 = (uint32_t)((la1 & 7) * 16);
            const uint32_t bbase = sb + OFF_B + j * 8192;

            #pragma unroll
            for (int ks = 0; ks < 4; ks++) {
                uint32_t a0[4], a1[4];
                {
                    uint32_t addr = r0base + ((uint32_t)((ks * 2 + a_uh) * 16) ^ sw0);
                    asm volatile("ldmatrix.sync.aligned.m8n8.x4.shared.b16 "
                                 "{%0,%1,%2,%3}, [%4];"
                                 : "=r"(a0[0]), "=r"(a0[1]), "=r"(a0[2]), "=r"(a0[3])
                                 : "r"(addr));
                    addr = r1base + ((uint32_t)((ks * 2 + a_uh) * 16) ^ sw1);
                    asm volatile("ldmatrix.sync.aligned.m8n8.x4.shared.b16 "
                                 "{%0,%1,%2,%3}, [%4];"
                                 : "=r"(a1[0]), "=r"(a1[1]), "=r"(a1[2]), "=r"(a1[3])
                                 : "r"(addr));
                }
                uint32_t bf[4][2];
                {
                    int nn = n_warp * 32 + b_n;
                    uint32_t addr = bbase + (uint32_t)(nn * 128 +
                                    (((ks * 2 + b_uh) ^ (nn & 7)) * 16));
                    asm volatile("ldmatrix.sync.aligned.m8n8.x4.shared.b16 "
                                 "{%0,%1,%2,%3}, [%4];"
                                 : "=r"(bf[0][0]), "=r"(bf[0][1]),
                                   "=r"(bf[1][0]), "=r"(bf[1][1])
                                 : "r"(addr));
                    nn += 16;
                    addr = bbase + (uint32_t)(nn * 128 +
                           (((ks * 2 + b_uh) ^ (nn & 7)) * 16));
                    asm volatile("ldmatrix.sync.aligned.m8n8.x4.shared.b16 "
                                 "{%0,%1,%2,%3}, [%4];"
                                 : "=r"(bf[2][0]), "=r"(bf[2][1]),
                                   "=r"(bf[3][0]), "=r"(bf[3][1])
                                 : "r"(addr));
                }
                #pragma unroll
                for (int nt = 0; nt < 4; nt++) {
                    asm volatile("mma.sync.aligned.m16n8k16.row.col.f32.f16.f16.f32 "
                                 "{%0,%1,%2,%3}, {%4,%5,%6,%7}, {%8,%9}, {%0,%1,%2,%3};"
                                 : "+f"(d[0][nt][0]), "+f"(d[0][nt][1]),
                                   "+f"(d[0][nt][2]), "+f"(d[0][nt][3])
                                 : "r"(a0[0]), "r"(a0[1]), "r"(a0[2]), "r"(a0[3]),
                                   "r"(bf[nt][0]), "r"(bf[nt][1]));
                    asm volatile("mma.sync.aligned.m16n8k16.row.col.f32.f16.f16.f32 "
                                 "{%0,%1,%2,%3}, {%4,%5,%6,%7}, {%8,%9}, {%0,%1,%2,%3};"
                                 : "+f"(d[1][nt][0]), "+f"(d[1][nt][1]),
                                   "+f"(d[1][nt][2]), "+f"(d[1][nt][3])
                                 : "r"(a1[0]), "r"(a1[1]), "r"(a1[2]), "r"(a1[3]),
                                   "r"(bf[nt][0]), "r"(bf[nt][1]));
                }
            }
        }

        // ---- epilogue: BN + ReLU + store (overlaps with next tile's cp.async) ----
        #pragma unroll
        for (int m16 = 0; m16 < 2; m16++) {
            #pragma unroll
            for (int nt = 0; nt < 4; nt++) {
                #pragma unroll
                for (int e = 0; e < 4; e++) {
                    int rloc = m_warp * 32 + m16 * 16 + (lane >> 2) + ((e >> 1) << 3);
                    int c    = n_warp * 32 + nt * 8 + (lane & 3) * 2 + (e & 1);
                    int pp   = p0 + rloc;
                    int r0   = pp / 48;
                    int er   = bh * 48 + r0;
                    int ec   = bw * 48 + (pp - r0 * 48);
                    float v  = fmaxf(fmaf(d[m16][nt][e], ssc[c], sbi[c]), 0.f);
                    out[((size_t)(n * 64 + c) * HH + er) * WW + ec] = v;
                }
            }
        }
    }
}

// ---------------------------------------------------------------------------
extern "C" void kernel_launch(void* const* d_in, const int* in_sizes, int n_in,
                              void* d_out, int out_size) {
    const float* x      = (const float*)d_in[0];
    const float* conv_w = (const float*)d_in[1];
    const float* conv_b = (const float*)d_in[2];
    const float* gamma  = (const float*)d_in[3];
    const float* beta   = (const float*)d_in[4];
    const float* rmean  = (const float*)d_in[5];
    const float* rvar   = (const float*)d_in[6];
    const int*   abi    = (const int*)d_in[7];
    float* out = (float*)d_out;

    int nblk = in_sizes[7] / 3;   // 256

    cudaFuncSetAttribute(conv_kernel,
                         cudaFuncAttributeMaxDynamicSharedMemorySize, SMEM_TOTAL);

    prep_kernel<<<36, 1024>>>(conv_w, conv_b, gamma, beta, rmean, rvar);
    mask_kernel<<<1, 512>>>(abi, nblk);
    patch_kernel<<<dim3(25, nblk), 512>>>(x, abi);
    conv_kernel<<<512, 512, SMEM_TOTAL>>>(abi, out, nblk);
}